// round 6
// baseline (speedup 1.0000x reference)
#include <cuda_runtime.h>
#include <cstdint>

#define NUM_INPUT  700
#define NUM_HIDDEN 256
#define NUM_OUTPUT 20
#define WIN        50
#define BATCH      512
#define THRESH     0.3f
#define ALPHA      0.8f

#define M_ROWS (BATCH * WIN)   // 25600

typedef unsigned long long ull;

// ---------------- f32x2 helpers ----------------
__device__ __forceinline__ ull pack2(float x, float y) {
    ull r; asm("mov.b64 %0, {%1, %2};" : "=l"(r) : "f"(x), "f"(y)); return r;
}
__device__ __forceinline__ void unpack2(ull v, float& x, float& y) {
    asm("mov.b64 {%0, %1}, %2;" : "=f"(x), "=f"(y) : "l"(v));
}
__device__ __forceinline__ void ffma2(ull& d, ull a, ull b) {   // d = a*b + d
    asm("fma.rn.f32x2 %0, %1, %2, %0;" : "+l"(d) : "l"(a), "l"(b));
}
__device__ __forceinline__ ull fma2n(ull a, ull b, ull c) {     // a*b + c
    ull d; asm("fma.rn.f32x2 %0, %1, %2, %3;" : "=l"(d) : "l"(a), "l"(b), "l"(c)); return d;
}
__device__ __forceinline__ ull add2(ull a, ull b) {
    ull d; asm("add.rn.f32x2 %0, %1, %2;" : "=l"(d) : "l"(a), "l"(b)); return d;
}

// ---------------- device scratch ----------------
__device__ float g_WcT[3 * NUM_INPUT * NUM_HIDDEN];
__device__ float g_WfT[2 * NUM_HIDDEN * NUM_HIDDEN];
__device__ float g_WrT[2 * NUM_HIDDEN * NUM_HIDDEN];
__device__ float g_WoT[NUM_HIDDEN * NUM_OUTPUT];
__device__ float g_cvec[NUM_HIDDEN];
__device__ float g_ff0[M_ROWS * NUM_HIDDEN];

// ---------------- prep kernels (R3, known-good) ----------------
__global__ void prep_transpose(const float* __restrict__ Wf,
                               const float* __restrict__ Wr,
                               const float* __restrict__ Wo) {
    int idx = blockIdx.x * 256 + threadIdx.x;
    if (idx < 2 * 256 * 256) {
        int h = idx & 255;
        int k = (idx >> 8) & 255;
        int l = idx >> 16;
        g_WfT[(l * 256 + k) * 256 + h] = Wf[(l * 256 + h) * 256 + k];
        g_WrT[(l * 256 + k) * 256 + h] = Wr[(l * 256 + h) * 256 + k];
    }
    if (idx < 256 * 20) {
        int o = idx % 20;
        int k = idx / 20;
        g_WoT[k * 20 + o] = Wo[o * 256 + k];
    }
}

__global__ void prep_wc(const float* __restrict__ Wd) {
    int ik = blockIdx.x;
    int i = ik / NUM_INPUT;
    int k = ik % NUM_INPUT;
    int h = threadIdx.x;
    float s = 0.f;
#pragma unroll 8
    for (int j = 0; j < 256; j++) {
        s += g_WfT[j * 256 + h] * __ldg(&Wd[(i * 256 + j) * NUM_INPUT + k]);
    }
    g_WcT[(i * NUM_INPUT + k) * 256 + h] = s;
}

__global__ void prep_cvec(const float* __restrict__ bd, const float* __restrict__ bf) {
    int h = threadIdx.x;
    float s = bf[h];
#pragma unroll 8
    for (int j = 0; j < 256; j++) {
        float bsum = bd[j] + bd[256 + j] + bd[512 + j];
        s += bsum * g_WfT[j * 256 + h];
    }
    g_cvec[h] = s;
}

// ---------------- ff0 GEMM (exact R3 version, 613us known) ----------------
#define GA_BM 128
#define GA_BN 64
#define GA_BK 16

__global__ __launch_bounds__(256) void gemm_ff0(const float* __restrict__ x) {
    __shared__ float As[GA_BK][GA_BM + 4];
    __shared__ float Bs[GA_BK][GA_BN];

    const int tid = threadIdx.x;
    const int rowBase = blockIdx.y * GA_BM;
    const int colBase = blockIdx.x * GA_BN;
    const int tx = tid & 15;
    const int ty = tid >> 4;

    ull accp[4][4];
#pragma unroll
    for (int p = 0; p < 4; p++)
#pragma unroll
        for (int j = 0; j < 4; j++) accp[p][j] = 0ull;

    const int delays[3] = {0, 16, 32};

    const int mm = tid >> 2;
    const int kq = (tid & 3) * 4;
    const int kkB = tid >> 4;
    const int hhB = (tid & 15) * 4;

    for (int i = 0; i < 3; i++) {
        const int d = delays[i];
        const float* __restrict__ Bsrc = &g_WcT[i * NUM_INPUT * 256];

        for (int kb = 0; kb < 704; kb += GA_BK) {
            int kg = kb + kq;
            bool kvalid = (kg < NUM_INPUT);
#pragma unroll
            for (int half = 0; half < 2; half++) {
                int r = rowBase + mm + half * 64;
                int b = r / WIN;
                int t = r - b * WIN;
                int ts = t - d;
                float4 v = make_float4(0.f, 0.f, 0.f, 0.f);
                if (ts >= 0 && kvalid)
                    v = *reinterpret_cast<const float4*>(x + (b * WIN + ts) * NUM_INPUT + kg);
                As[kq + 0][mm + half * 64] = v.x;
                As[kq + 1][mm + half * 64] = v.y;
                As[kq + 2][mm + half * 64] = v.z;
                As[kq + 3][mm + half * 64] = v.w;
            }
            int kg2 = kb + kkB;
            float4 w = make_float4(0.f, 0.f, 0.f, 0.f);
            if (kg2 < NUM_INPUT)
                w = *reinterpret_cast<const float4*>(Bsrc + kg2 * 256 + colBase + hhB);
            *reinterpret_cast<float4*>(&Bs[kkB][hhB]) = w;

            __syncthreads();

#pragma unroll
            for (int kk = 0; kk < GA_BK; kk++) {
                ulonglong2 a0p = *reinterpret_cast<const ulonglong2*>(&As[kk][ty * 8 + 0]);
                ulonglong2 a1p = *reinterpret_cast<const ulonglong2*>(&As[kk][ty * 8 + 4]);
                float4 bb = *reinterpret_cast<const float4*>(&Bs[kk][tx * 4]);
                ull bp[4] = {pack2(bb.x, bb.x), pack2(bb.y, bb.y),
                             pack2(bb.z, bb.z), pack2(bb.w, bb.w)};
                ull ap[4] = {a0p.x, a0p.y, a1p.x, a1p.y};
#pragma unroll
                for (int p = 0; p < 4; p++)
#pragma unroll
                    for (int j = 0; j < 4; j++) ffma2(accp[p][j], ap[p], bp[j]);
            }
            __syncthreads();
        }
    }

#pragma unroll
    for (int p = 0; p < 4; p++) {
#pragma unroll
        for (int j = 0; j < 4; j++) {
            float v0, v1;
            unpack2(accp[p][j], v0, v1);
            int c = colBase + tx * 4 + j;
            int r0 = rowBase + ty * 8 + 2 * p;
            g_ff0[(size_t)r0 * 256 + c] = v0 + g_cvec[c];
            g_ff0[(size_t)(r0 + 1) * 256 + c] = v1 + g_cvec[c];
        }
    }
}

// ---------------- cluster scan ----------------
// 32 clusters x 8 CTAs x 256 threads. Cluster owns 16 batch rows.
// CTA rank owns h-slice [rank*32, rank*32+32) and holds its slice of all
// 3 weight matrices in smem. Spikes (full 256 h x 8 row-pairs) replicated in
// every CTA; new spikes pushed to all peers via st.shared::cluster.
#define CL 8
#define RR 16     // rows per cluster

// smem float offsets
#define SOFF_W    0                       // [3][256][32] = 24576
#define SOFF_SP0  24576                   // [2][256][16] = 8192
#define SOFF_SP1  (SOFF_SP0 + 8192)       // 32768
#define SOFF_WOT  (SOFF_SP1 + 8192)       // 40960  [256][20] = 5120
#define SOFF_PART (SOFF_WOT + 5120)       // 46080  [8 pair][8 ks][32 hl] ull = 4096 floats
#define SOFF_OSM  (SOFF_PART + 4096)      // 50176  (40)
#define SOFF_OTMP (SOFF_OSM + 40)         // 50216  (40)
#define SOFF_OSUM (SOFF_OTMP + 40)        // 50256  (2 + pad)
#define SCAN_FLOATS (SOFF_OSUM + 8)       // 50264 floats = 201056 bytes

#define CLUSTER_SYNC() do { \
    asm volatile("barrier.cluster.arrive.aligned;" ::: "memory"); \
    asm volatile("barrier.cluster.wait.aligned;" ::: "memory"); \
} while (0)

__device__ __forceinline__ void push_all(uint32_t laddr, ull v) {
#pragma unroll
    for (int r = 0; r < CL; r++) {
        uint32_t ra;
        asm volatile("mapa.shared::cluster.u32 %0, %1, %2;" : "=r"(ra) : "r"(laddr), "r"(r));
        asm volatile("st.shared::cluster.u64 [%0], %1;" :: "r"(ra), "l"(v) : "memory");
    }
}

// accumulate one matrix pass over this thread's k-slice
__device__ __forceinline__ void scan_pass(ull acc[8], const float* __restrict__ wsl,
                                          const float* __restrict__ spf,
                                          int kb, int hl) {
#pragma unroll 4
    for (int k = kb; k < kb + 32; k++) {
        float w = wsl[k * 32 + hl];
        ull wp = pack2(w, w);
        const ulonglong2* sq = (const ulonglong2*)(spf + k * 16);
        ulonglong2 q0 = sq[0], q1 = sq[1], q2 = sq[2], q3 = sq[3];
        ffma2(acc[0], wp, q0.x); ffma2(acc[1], wp, q0.y);
        ffma2(acc[2], wp, q1.x); ffma2(acc[3], wp, q1.y);
        ffma2(acc[4], wp, q2.x); ffma2(acc[5], wp, q2.y);
        ffma2(acc[6], wp, q3.x); ffma2(acc[7], wp, q3.y);
    }
}

__global__ __launch_bounds__(256) __cluster_dims__(CL, 1, 1)
void scan_kernel(const float* __restrict__ bf,
                 const float* __restrict__ bo,
                 float* __restrict__ out) {
    extern __shared__ float sm[];
    uint32_t smem_u32;
    asm("{ .reg .u64 t; cvta.to.shared.u64 t, %1; cvt.u32.u64 %0, t; }"
        : "=r"(smem_u32) : "l"(sm));

    const int tid = threadIdx.x;
    uint32_t rank;
    asm("mov.u32 %0, %%cluster_ctarank;" : "=r"(rank));
    const int cid = blockIdx.x >> 3;
    const int b0 = cid * RR;

    const int hl = tid & 31;       // local h (also used in reduce role)
    const int ks = tid >> 5;       // k-slice (pass role) / pair index (reduce role)
    const int hg = (int)rank * 32 + hl;

    float* Wsh  = sm + SOFF_W;
    float* sp0f = sm + SOFF_SP0;
    float* sp1f = sm + SOFF_SP1;
    float* wot  = sm + SOFF_WOT;
    ull*   partq = (ull*)(sm + SOFF_PART);
    float* osm  = sm + SOFF_OSM;
    float* otmp = sm + SOFF_OTMP;
    float* osum = sm + SOFF_OSUM;

    // ---- init: weights slice, wot, zero spikes ----
    {
        const float* s0 = g_WrT;                 // layer0 Wr^T
        const float* s1 = g_WfT + 65536;         // layer1 Wf^T
        const float* s2 = g_WrT + 65536;         // layer1 Wr^T
        for (int idx = tid; idx < 8192; idx += 256) {
            int k = idx >> 5, h2 = idx & 31;
            Wsh[idx]         = __ldg(s0 + k * 256 + (int)rank * 32 + h2);
            Wsh[8192 + idx]  = __ldg(s1 + k * 256 + (int)rank * 32 + h2);
            Wsh[16384 + idx] = __ldg(s2 + k * 256 + (int)rank * 32 + h2);
        }
        for (int idx = tid; idx < 5120; idx += 256) wot[idx] = g_WoT[idx];
        for (int idx = tid; idx < 8192; idx += 256) { sp0f[idx] = 0.f; sp1f[idx] = 0.f; }
    }

    // membrane state (reduce role: h=hg, rows 2*ks, 2*ks+1)
    ull m0 = 0ull, m1 = 0ull;
    const ull alpha2 = pack2(ALPHA, ALPHA);
    ull df0 = alpha2, df1 = alpha2;
    const float bf1h = __ldg(bf + 256 + hg);
    const ull bf1p = pack2(bf1h, bf1h);

    // ff0 pointers for reduce role
    const float* ffp0 = g_ff0 + (size_t)(b0 + 2 * ks) * WIN * 256 + hg;
    const float* ffp1 = g_ff0 + (size_t)(b0 + 2 * ks + 1) * WIN * 256 + hg;

    // output role: tid<40 -> (ol = row within rank pair, ocol)
    const int ol = (tid < 40) ? (tid / 20) : 0;
    const int ocol = (tid < 40) ? (tid - ol * 20) : 0;
    const int orowg = b0 + 2 * (int)rank + ol;
    const float bov = (tid < 40) ? __ldg(bo + ocol) : 0.f;
    float o_mem = 0.f, o_dfac = ALPHA, o_sumv = 0.f, o_mot = 0.f;

    CLUSTER_SYNC();    // all CTAs initialized before any DSMEM pushes

    for (int t = 0; t < WIN; t++) {
        const int ri = t & 1, wi = 1 - ri;
        const float* s0_old = sp0f + ri * 4096;
        const float* s0_new = sp0f + wi * 4096;
        const float* s1_old = sp1f + ri * 4096;
        const float* s1_new = sp1f + wi * 4096;

        // ---- phase A: layer0 partials over k-slice ----
        ull acc[8];
#pragma unroll
        for (int p = 0; p < 8; p++) acc[p] = 0ull;
        scan_pass(acc, Wsh, s0_old, ks * 32, hl);
#pragma unroll
        for (int p = 0; p < 8; p++) partq[p * 256 + ks * 32 + hl] = acc[p];
        __syncthreads();

        // ---- phase B: reduce + membrane0 + spike push ----
        {
            ull r = 0ull;
#pragma unroll
            for (int j = 0; j < 8; j++) r = add2(r, partq[ks * 256 + j * 32 + hl]);
            float fa = __ldg(ffp0 + t * 256);
            float fb = __ldg(ffp1 + t * 256);
            r = add2(r, pack2(fa, fb));
            m0 = fma2n(m0, df0, r);
            float mx, my; unpack2(m0, mx, my);
            float sx = (mx - THRESH > 0.f) ? 1.f : 0.f;
            float sy = (my - THRESH > 0.f) ? 1.f : 0.f;
            df0 = pack2(ALPHA * (1.f - sx), ALPHA * (1.f - sy));
            uint32_t laddr = smem_u32 + (SOFF_SP0 + wi * 4096 + hg * 16 + ks * 2) * 4;
            push_all(laddr, pack2(sx, sy));
        }
        CLUSTER_SYNC();   // s0_new complete everywhere

        // ---- phase C: layer1 partials (ff over s0_new + rec over s1_old) ----
#pragma unroll
        for (int p = 0; p < 8; p++) acc[p] = 0ull;
        scan_pass(acc, Wsh + 8192, s0_new, ks * 32, hl);
        scan_pass(acc, Wsh + 16384, s1_old, ks * 32, hl);
#pragma unroll
        for (int p = 0; p < 8; p++) partq[p * 256 + ks * 32 + hl] = acc[p];
        __syncthreads();

        // ---- phase D: reduce + membrane1 + spike push ----
        {
            ull r = bf1p;
#pragma unroll
            for (int j = 0; j < 8; j++) r = add2(r, partq[ks * 256 + j * 32 + hl]);
            m1 = fma2n(m1, df1, r);
            float mx, my; unpack2(m1, mx, my);
            float sx = (mx - THRESH > 0.f) ? 1.f : 0.f;
            float sy = (my - THRESH > 0.f) ? 1.f : 0.f;
            df1 = pack2(ALPHA * (1.f - sx), ALPHA * (1.f - sy));
            uint32_t laddr = smem_u32 + (SOFF_SP1 + wi * 4096 + hg * 16 + ks * 2) * 4;
            push_all(laddr, pack2(sx, sy));
        }
        CLUSTER_SYNC();   // s1_new complete everywhere

        // ---- phase E: output (rank handles rows 2*rank, 2*rank+1) ----
        if (tid < 40) {
            float oa = bov;
            const int base = 2 * (int)rank + ol;   // float offset within 16-wide row group
#pragma unroll 8
            for (int k = 0; k < 256; k++)
                oa += s1_new[k * 16 + base] * wot[k * 20 + ocol];
            o_mem = o_mem * o_dfac + oa;
            float os = (o_mem - THRESH > 0.f) ? 1.f : 0.f;
            o_dfac = ALPHA * (1.f - os);
            o_sumv += os;
            osm[ol * 20 + ocol] = o_mem;
        }
        __syncthreads();
        if (tid < 2) {
            float mxv = -1e30f;
#pragma unroll
            for (int o = 0; o < 20; o++) mxv = fmaxf(mxv, osm[tid * 20 + o]);
            float s = 0.f;
#pragma unroll
            for (int o = 0; o < 20; o++) {
                float e = expf(osm[tid * 20 + o] - mxv);
                otmp[tid * 20 + o] = e;
                s += e;
            }
            osum[tid] = s;
        }
        __syncthreads();
        if (tid < 40) {
            o_mot += otmp[ol * 20 + ocol] / osum[ol];
        }
        // next phase A only touches partq / spike buffers -> safe without extra sync
    }

    if (tid < 40) {
        out[orowg * 20 + ocol] = o_sumv / (float)WIN;
        out[BATCH * 20 + orowg * 20 + ocol] = o_mot;
    }
}

// ---------------- launch ----------------
extern "C" void kernel_launch(void* const* d_in, const int* in_sizes, int n_in,
                              void* d_out, int out_size) {
    const float* x  = (const float*)d_in[0];
    const float* Wd = (const float*)d_in[1];
    const float* bd = (const float*)d_in[2];
    const float* Wf = (const float*)d_in[3];
    const float* bf = (const float*)d_in[4];
    const float* Wr = (const float*)d_in[5];
    const float* Wo = (const float*)d_in[6];
    const float* bo = (const float*)d_in[7];
    float* out = (float*)d_out;

    static bool attr_set = false;
    if (!attr_set) {
        cudaFuncSetAttribute(scan_kernel, cudaFuncAttributeMaxDynamicSharedMemorySize,
                             SCAN_FLOATS * 4);
        attr_set = true;
    }

    prep_transpose<<<512, 256>>>(Wf, Wr, Wo);
    prep_wc<<<3 * NUM_INPUT, 256>>>(Wd);
    prep_cvec<<<1, 256>>>(bd, bf);
    gemm_ff0<<<dim3(NUM_HIDDEN / GA_BN, M_ROWS / GA_BM), 256>>>(x);
    scan_kernel<<<(BATCH / RR) * CL, 256, SCAN_FLOATS * 4>>>(bf, bo, out);
}

// round 7
// speedup vs baseline: 1.6531x; 1.6531x over previous
#include <cuda_runtime.h>
#include <cstdint>

#define NUM_INPUT  700
#define NUM_HIDDEN 256
#define NUM_OUTPUT 20
#define WIN        50
#define BATCH      512
#define THRESH     0.3f
#define ALPHA      0.8f

#define M_ROWS (BATCH * WIN)   // 25600

typedef unsigned long long ull;

// ---------------- f32x2 helpers ----------------
__device__ __forceinline__ ull pack2(float x, float y) {
    ull r; asm("mov.b64 %0, {%1, %2};" : "=l"(r) : "f"(x), "f"(y)); return r;
}
__device__ __forceinline__ void unpack2(ull v, float& x, float& y) {
    asm("mov.b64 {%0, %1}, %2;" : "=f"(x), "=f"(y) : "l"(v));
}
__device__ __forceinline__ void ffma2(ull& d, ull a, ull b) {   // d = a*b + d
    asm("fma.rn.f32x2 %0, %1, %2, %0;" : "+l"(d) : "l"(a), "l"(b));
}
__device__ __forceinline__ ull fma2n(ull a, ull b, ull c) {     // a*b + c
    ull d; asm("fma.rn.f32x2 %0, %1, %2, %3;" : "=l"(d) : "l"(a), "l"(b), "l"(c)); return d;
}
__device__ __forceinline__ ull add2(ull a, ull b) {
    ull d; asm("add.rn.f32x2 %0, %1, %2;" : "=l"(d) : "l"(a), "l"(b)); return d;
}
__device__ __forceinline__ ulonglong2 ldg128(const float* p) {
    ulonglong2 v;
    asm("ld.global.nc.v2.u64 {%0, %1}, [%2];" : "=l"(v.x), "=l"(v.y) : "l"(p));
    return v;
}

// ---------------- device scratch ----------------
__device__ float g_WcT[3 * NUM_INPUT * NUM_HIDDEN];
__device__ float g_WfT[2 * NUM_HIDDEN * NUM_HIDDEN];
__device__ float g_WrT[2 * NUM_HIDDEN * NUM_HIDDEN];
__device__ float g_WoT[NUM_HIDDEN * NUM_OUTPUT];
__device__ float g_cvec[NUM_HIDDEN];
__device__ float g_ff0[M_ROWS * NUM_HIDDEN];

// ---------------- prep kernels ----------------
__global__ void prep_transpose(const float* __restrict__ Wf,
                               const float* __restrict__ Wr,
                               const float* __restrict__ Wo) {
    int idx = blockIdx.x * 256 + threadIdx.x;
    if (idx < 2 * 256 * 256) {
        int h = idx & 255;
        int k = (idx >> 8) & 255;
        int l = idx >> 16;
        g_WfT[(l * 256 + k) * 256 + h] = Wf[(l * 256 + h) * 256 + k];
        g_WrT[(l * 256 + k) * 256 + h] = Wr[(l * 256 + h) * 256 + k];
    }
    if (idx < 256 * 20) {
        int o = idx % 20;
        int k = idx / 20;
        g_WoT[k * 20 + o] = Wo[o * 256 + k];
    }
}

__global__ void prep_wc(const float* __restrict__ Wd) {
    int ik = blockIdx.x;
    int i = ik / NUM_INPUT;
    int k = ik % NUM_INPUT;
    int h = threadIdx.x;
    float s = 0.f;
#pragma unroll 8
    for (int j = 0; j < 256; j++) {
        s += g_WfT[j * 256 + h] * __ldg(&Wd[(i * 256 + j) * NUM_INPUT + k]);
    }
    g_WcT[(i * NUM_INPUT + k) * 256 + h] = s;
}

__global__ void prep_cvec(const float* __restrict__ bd, const float* __restrict__ bf) {
    int h = threadIdx.x;
    float s = bf[h];
#pragma unroll 8
    for (int j = 0; j < 256; j++) {
        float bsum = bd[j] + bd[256 + j] + bd[512 + j];
        s += bsum * g_WfT[j * 256 + h];
    }
    g_cvec[h] = s;
}

// ---------------- ff0 GEMM (R3 exact, 613us known) ----------------
#define GA_BM 128
#define GA_BN 64
#define GA_BK 16

__global__ __launch_bounds__(256) void gemm_ff0(const float* __restrict__ x) {
    __shared__ float As[GA_BK][GA_BM + 4];
    __shared__ float Bs[GA_BK][GA_BN];

    const int tid = threadIdx.x;
    const int rowBase = blockIdx.y * GA_BM;
    const int colBase = blockIdx.x * GA_BN;
    const int tx = tid & 15;
    const int ty = tid >> 4;

    ull accp[4][4];
#pragma unroll
    for (int p = 0; p < 4; p++)
#pragma unroll
        for (int j = 0; j < 4; j++) accp[p][j] = 0ull;

    const int delays[3] = {0, 16, 32};

    const int mm = tid >> 2;
    const int kq = (tid & 3) * 4;
    const int kkB = tid >> 4;
    const int hhB = (tid & 15) * 4;

    for (int i = 0; i < 3; i++) {
        const int d = delays[i];
        const float* __restrict__ Bsrc = &g_WcT[i * NUM_INPUT * 256];

        for (int kb = 0; kb < 704; kb += GA_BK) {
            int kg = kb + kq;
            bool kvalid = (kg < NUM_INPUT);
#pragma unroll
            for (int half = 0; half < 2; half++) {
                int r = rowBase + mm + half * 64;
                int b = r / WIN;
                int t = r - b * WIN;
                int ts = t - d;
                float4 v = make_float4(0.f, 0.f, 0.f, 0.f);
                if (ts >= 0 && kvalid)
                    v = *reinterpret_cast<const float4*>(x + (b * WIN + ts) * NUM_INPUT + kg);
                As[kq + 0][mm + half * 64] = v.x;
                As[kq + 1][mm + half * 64] = v.y;
                As[kq + 2][mm + half * 64] = v.z;
                As[kq + 3][mm + half * 64] = v.w;
            }
            int kg2 = kb + kkB;
            float4 w = make_float4(0.f, 0.f, 0.f, 0.f);
            if (kg2 < NUM_INPUT)
                w = *reinterpret_cast<const float4*>(Bsrc + kg2 * 256 + colBase + hhB);
            *reinterpret_cast<float4*>(&Bs[kkB][hhB]) = w;

            __syncthreads();

#pragma unroll
            for (int kk = 0; kk < GA_BK; kk++) {
                ulonglong2 a0p = *reinterpret_cast<const ulonglong2*>(&As[kk][ty * 8 + 0]);
                ulonglong2 a1p = *reinterpret_cast<const ulonglong2*>(&As[kk][ty * 8 + 4]);
                float4 bb = *reinterpret_cast<const float4*>(&Bs[kk][tx * 4]);
                ull bp[4] = {pack2(bb.x, bb.x), pack2(bb.y, bb.y),
                             pack2(bb.z, bb.z), pack2(bb.w, bb.w)};
                ull ap[4] = {a0p.x, a0p.y, a1p.x, a1p.y};
#pragma unroll
                for (int p = 0; p < 4; p++)
#pragma unroll
                    for (int j = 0; j < 4; j++) ffma2(accp[p][j], ap[p], bp[j]);
            }
            __syncthreads();
        }
    }

#pragma unroll
    for (int p = 0; p < 4; p++) {
#pragma unroll
        for (int j = 0; j < 4; j++) {
            float v0, v1;
            unpack2(accp[p][j], v0, v1);
            int c = colBase + tx * 4 + j;
            int r0 = rowBase + ty * 8 + 2 * p;
            g_ff0[(size_t)r0 * 256 + c] = v0 + g_cvec[c];
            g_ff0[(size_t)(r0 + 1) * 256 + c] = v1 + g_cvec[c];
        }
    }
}

// ---------------- recurrent scan (R4 skeleton + register weight prefetch) ----
// 64 blocks x 512 threads. Thread = (ks = tid>>6 in 0..7, hq = tid&63 -> 4 h).
// Spikes PRE-DUPLICATED: sp[h][2r],[2r+1] = s  (stride 20 floats per h).
#define OFFP    0                      // partials: 8*8*64 ulonglong2 = 16384 floats
#define OFFS0   16384                  // sp0 dup: 256*20 = 5120
#define OFFS1   (OFFS0 + 5120)
#define OFFWOT  (OFFS1 + 5120)
#define OFFOSM  (OFFWOT + 5120)
#define OFFOTMP (OFFOSM + 160)
#define SCAN_FLOATS (OFFOTMP + 160)    // 32064 floats = 128256 bytes

// accumulate 32 k's (this thread's slice) with explicit 4-k-chunk register
// double-buffered weight prefetch (MLP=4, hides L2 latency).
__device__ __forceinline__ void accum_quad_pf(ull acc[8][2], const float* __restrict__ wg,
                                              int hq4, const float* __restrict__ sp, int kbeg) {
    const float* wp = wg + (size_t)kbeg * 256 + hq4;
    ulonglong2 wbuf[2][4];
#pragma unroll
    for (int c = 0; c < 4; c++) wbuf[0][c] = ldg128(wp + c * 256);
#pragma unroll
    for (int j = 0; j < 8; j++) {
        const int cur = j & 1, nxt = cur ^ 1;
        if (j < 7) {
            const float* q = wp + (size_t)((j + 1) * 4) * 256;
#pragma unroll
            for (int c = 0; c < 4; c++) wbuf[nxt][c] = ldg128(q + c * 256);
        }
#pragma unroll
        for (int c = 0; c < 4; c++) {
            const int k = kbeg + j * 4 + c;
            const ulonglong2* sq = (const ulonglong2*)(sp + k * 20);
            ulonglong2 s01 = sq[0], s23 = sq[1], s45 = sq[2], s67 = sq[3];
            ulonglong2 w = wbuf[cur][c];
            ffma2(acc[0][0], w.x, s01.x); ffma2(acc[0][1], w.y, s01.x);
            ffma2(acc[1][0], w.x, s01.y); ffma2(acc[1][1], w.y, s01.y);
            ffma2(acc[2][0], w.x, s23.x); ffma2(acc[2][1], w.y, s23.x);
            ffma2(acc[3][0], w.x, s23.y); ffma2(acc[3][1], w.y, s23.y);
            ffma2(acc[4][0], w.x, s45.x); ffma2(acc[4][1], w.y, s45.x);
            ffma2(acc[5][0], w.x, s45.y); ffma2(acc[5][1], w.y, s45.y);
            ffma2(acc[6][0], w.x, s67.x); ffma2(acc[6][1], w.y, s67.x);
            ffma2(acc[7][0], w.x, s67.y); ffma2(acc[7][1], w.y, s67.y);
        }
    }
}

__global__ __launch_bounds__(512) void scan_kernel(const float* __restrict__ bf,
                                                   const float* __restrict__ bo,
                                                   float* __restrict__ out) {
    extern __shared__ float sm[];
    ulonglong2* partq = (ulonglong2*)(sm + OFFP);
    float* sp0  = sm + OFFS0;
    float* sp1  = sm + OFFS1;
    float* wot  = sm + OFFWOT;
    float* opart = sm + OFFP;          // alias (barrier-separated)
    float* osm  = sm + OFFOSM;
    float* otmp = sm + OFFOTMP;

    const int tid = threadIdx.x;
    const int ks = tid >> 6;           // 0..7 (k-split AND owned row)
    const int hq = tid & 63;
    const int hq4 = hq * 4;
    const int b0 = blockIdx.x * 8;

    for (int i = tid; i < 256 * 20; i += 512) wot[i] = g_WoT[i];
    for (int i = tid; i < 5120; i += 512) { sp0[i] = 0.f; sp1[i] = 0.f; }
    __syncthreads();

    ull m0a = 0, m0b = 0, m1a = 0, m1b = 0;
    const ull alpha2 = pack2(ALPHA, ALPHA);
    ull df0a = alpha2, df0b = alpha2, df1a = alpha2, df1b = alpha2;

    float4 bfq = __ldg((const float4*)(bf + 256 + hq4));
    const ull bf1a = pack2(bfq.x, bfq.y);
    const ull bf1b = pack2(bfq.z, bfq.w);

    const int seg = (tid >= 160 && tid < 320) ? 1 : 0;
    const int rr = (tid < 160) ? tid : (tid < 320 ? tid - 160 : 0);
    const int orow = rr / 20, ocol = rr - orow * 20;
    const int okbeg = seg * 128;
    const float bov = (tid < 160) ? __ldg(bo + ocol) : 0.f;
    float o_mem = 0.f, o_dfac = ALPHA, o_sumv = 0.f, o_mot = 0.f;

    const float* __restrict__ wr0g = g_WrT;
    const float* __restrict__ wf1g = g_WfT + 65536;
    const float* __restrict__ wr1g = g_WrT + 65536;

    const int kbeg = ks * 32;

    for (int t = 0; t < WIN; t++) {
        float4 ffv = __ldg((const float4*)(g_ff0 + ((size_t)(b0 + ks) * WIN + t) * 256 + hq4));

        // ---- stage 1: layer0 partials ----
        ull acc[8][2];
#pragma unroll
        for (int r = 0; r < 8; r++) { acc[r][0] = 0ull; acc[r][1] = 0ull; }
        accum_quad_pf(acc, wr0g, hq4, sp0, kbeg);
#pragma unroll
        for (int r = 0; r < 8; r++)
            partq[(r * 8 + ks) * 64 + hq] = make_ulonglong2(acc[r][0], acc[r][1]);
        __syncthreads();                                        // S1

        // ---- stage 2: reduce, membrane0, spikes ----
        {
            ull r0 = 0ull, r1 = 0ull;
#pragma unroll
            for (int j = 0; j < 8; j++) {
                ulonglong2 p = partq[(ks * 8 + j) * 64 + hq];
                r0 = add2(r0, p.x); r1 = add2(r1, p.y);
            }
            r0 = add2(r0, pack2(ffv.x, ffv.y));
            r1 = add2(r1, pack2(ffv.z, ffv.w));
            m0a = fma2n(m0a, df0a, r0);
            m0b = fma2n(m0b, df0b, r1);
            float mx, my, mz, mw;
            unpack2(m0a, mx, my); unpack2(m0b, mz, mw);
            float sx = (mx - THRESH > 0.f) ? 1.f : 0.f;
            float sy = (my - THRESH > 0.f) ? 1.f : 0.f;
            float sz = (mz - THRESH > 0.f) ? 1.f : 0.f;
            float sw = (mw - THRESH > 0.f) ? 1.f : 0.f;
            df0a = pack2(ALPHA * (1.f - sx), ALPHA * (1.f - sy));
            df0b = pack2(ALPHA * (1.f - sz), ALPHA * (1.f - sw));
            *(float2*)(sp0 + (hq4 + 0) * 20 + 2 * ks) = make_float2(sx, sx);
            *(float2*)(sp0 + (hq4 + 1) * 20 + 2 * ks) = make_float2(sy, sy);
            *(float2*)(sp0 + (hq4 + 2) * 20 + 2 * ks) = make_float2(sz, sz);
            *(float2*)(sp0 + (hq4 + 3) * 20 + 2 * ks) = make_float2(sw, sw);
        }
        __syncthreads();                                        // S2

        // ---- stage 3: layer1 partials ----
#pragma unroll
        for (int r = 0; r < 8; r++) { acc[r][0] = 0ull; acc[r][1] = 0ull; }
        accum_quad_pf(acc, wf1g, hq4, sp0, kbeg);
        accum_quad_pf(acc, wr1g, hq4, sp1, kbeg);
#pragma unroll
        for (int r = 0; r < 8; r++)
            partq[(r * 8 + ks) * 64 + hq] = make_ulonglong2(acc[r][0], acc[r][1]);
        __syncthreads();                                        // S3

        // ---- stage 4: reduce, membrane1, spikes ----
        {
            ull r0 = 0ull, r1 = 0ull;
#pragma unroll
            for (int j = 0; j < 8; j++) {
                ulonglong2 p = partq[(ks * 8 + j) * 64 + hq];
                r0 = add2(r0, p.x); r1 = add2(r1, p.y);
            }
            r0 = add2(r0, bf1a);
            r1 = add2(r1, bf1b);
            m1a = fma2n(m1a, df1a, r0);
            m1b = fma2n(m1b, df1b, r1);
            float mx, my, mz, mw;
            unpack2(m1a, mx, my); unpack2(m1b, mz, mw);
            float sx = (mx - THRESH > 0.f) ? 1.f : 0.f;
            float sy = (my - THRESH > 0.f) ? 1.f : 0.f;
            float sz = (mz - THRESH > 0.f) ? 1.f : 0.f;
            float sw = (mw - THRESH > 0.f) ? 1.f : 0.f;
            df1a = pack2(ALPHA * (1.f - sx), ALPHA * (1.f - sy));
            df1b = pack2(ALPHA * (1.f - sz), ALPHA * (1.f - sw));
            *(float2*)(sp1 + (hq4 + 0) * 20 + 2 * ks) = make_float2(sx, sx);
            *(float2*)(sp1 + (hq4 + 1) * 20 + 2 * ks) = make_float2(sy, sy);
            *(float2*)(sp1 + (hq4 + 2) * 20 + 2 * ks) = make_float2(sz, sz);
            *(float2*)(sp1 + (hq4 + 3) * 20 + 2 * ks) = make_float2(sw, sw);
        }
        __syncthreads();                                        // S4

        // ---- stage 5: output partials ----
        if (tid < 320) {
            float oa = 0.f;
#pragma unroll 8
            for (int k = okbeg; k < okbeg + 128; k++) {
                oa += sp1[k * 20 + 2 * orow] * wot[k * 20 + ocol];
            }
            opart[tid] = oa;
        }
        __syncthreads();                                        // S5

        // ---- stage 6: output membrane ----
        if (tid < 160) {
            float oa = opart[tid] + opart[tid + 160] + bov;
            o_mem = o_mem * o_dfac + oa;
            float os = (o_mem - THRESH > 0.f) ? 1.f : 0.f;
            o_dfac = ALPHA * (1.f - os);
            o_sumv += os;
            osm[tid] = o_mem;
        }
        __syncthreads();                                        // S6

        // ---- stage 7: distributed softmax: each of 160 threads does 1 expf ----
        float e = 0.f;
        if (tid < 160) {
            float mx = -1e30f;
#pragma unroll
            for (int o = 0; o < 20; o++) mx = fmaxf(mx, osm[orow * 20 + o]);
            e = expf(o_mem - mx);
            otmp[tid] = e;
        }
        __syncthreads();                                        // S7

        if (tid < 160) {
            float s = 0.f;
#pragma unroll
            for (int o = 0; o < 20; o++) s += otmp[orow * 20 + o];
            o_mot += e / s;
        }
        __syncthreads();                                        // S8
    }

    if (tid < 160) {
        int b = b0 + orow;
        out[b * 20 + ocol] = o_sumv / (float)WIN;
        out[BATCH * 20 + b * 20 + ocol] = o_mot;
    }
}

// ---------------- launch ----------------
extern "C" void kernel_launch(void* const* d_in, const int* in_sizes, int n_in,
                              void* d_out, int out_size) {
    const float* x  = (const float*)d_in[0];
    const float* Wd = (const float*)d_in[1];
    const float* bd = (const float*)d_in[2];
    const float* Wf = (const float*)d_in[3];
    const float* bf = (const float*)d_in[4];
    const float* Wr = (const float*)d_in[5];
    const float* Wo = (const float*)d_in[6];
    const float* bo = (const float*)d_in[7];
    float* out = (float*)d_out;

    static bool attr_set = false;
    if (!attr_set) {
        cudaFuncSetAttribute(scan_kernel, cudaFuncAttributeMaxDynamicSharedMemorySize,
                             SCAN_FLOATS * 4);
        attr_set = true;
    }

    prep_transpose<<<512, 256>>>(Wf, Wr, Wo);
    prep_wc<<<3 * NUM_INPUT, 256>>>(Wd);
    prep_cvec<<<1, 256>>>(bd, bf);
    gemm_ff0<<<dim3(NUM_HIDDEN / GA_BN, M_ROWS / GA_BM), 256>>>(x);
    scan_kernel<<<64, 512, SCAN_FLOATS * 4>>>(bf, bo, out);
}

// round 8
// speedup vs baseline: 1.8585x; 1.1242x over previous
#include <cuda_runtime.h>
#include <cstdint>

#define NUM_INPUT  700
#define NUM_HIDDEN 256
#define NUM_OUTPUT 20
#define WIN        50
#define BATCH      512
#define THRESH     0.3f
#define ALPHA      0.8f

#define M_ROWS (BATCH * WIN)   // 25600

typedef unsigned long long ull;

// ---------------- f32x2 helpers ----------------
__device__ __forceinline__ ull pack2(float x, float y) {
    ull r; asm("mov.b64 %0, {%1, %2};" : "=l"(r) : "f"(x), "f"(y)); return r;
}
__device__ __forceinline__ void unpack2(ull v, float& x, float& y) {
    asm("mov.b64 {%0, %1}, %2;" : "=f"(x), "=f"(y) : "l"(v));
}
__device__ __forceinline__ void ffma2(ull& d, ull a, ull b) {   // d = a*b + d
    asm("fma.rn.f32x2 %0, %1, %2, %0;" : "+l"(d) : "l"(a), "l"(b));
}
__device__ __forceinline__ ull fma2n(ull a, ull b, ull c) {     // a*b + c
    ull d; asm("fma.rn.f32x2 %0, %1, %2, %3;" : "=l"(d) : "l"(a), "l"(b), "l"(c)); return d;
}
__device__ __forceinline__ ull add2(ull a, ull b) {
    ull d; asm("add.rn.f32x2 %0, %1, %2;" : "=l"(d) : "l"(a), "l"(b)); return d;
}
__device__ __forceinline__ ulonglong2 ldg128(const float* p) {
    ulonglong2 v;
    asm("ld.global.nc.v2.u64 {%0, %1}, [%2];" : "=l"(v.x), "=l"(v.y) : "l"(p));
    return v;
}

// ---------------- device scratch ----------------
__device__ float g_WcT[3 * NUM_INPUT * NUM_HIDDEN];
__device__ float g_WfT[2 * NUM_HIDDEN * NUM_HIDDEN];
__device__ float g_WrT[2 * NUM_HIDDEN * NUM_HIDDEN];
__device__ float g_WoT[NUM_HIDDEN * NUM_OUTPUT];
__device__ float g_cvec[NUM_HIDDEN];
__device__ float g_ff0[M_ROWS * NUM_HIDDEN];

// ---------------- prep kernels ----------------
__global__ void prep_transpose(const float* __restrict__ Wf,
                               const float* __restrict__ Wr,
                               const float* __restrict__ Wo) {
    int idx = blockIdx.x * 256 + threadIdx.x;
    if (idx < 2 * 256 * 256) {
        int h = idx & 255;
        int k = (idx >> 8) & 255;
        int l = idx >> 16;
        g_WfT[(l * 256 + k) * 256 + h] = Wf[(l * 256 + h) * 256 + k];
        g_WrT[(l * 256 + k) * 256 + h] = Wr[(l * 256 + h) * 256 + k];
    }
    if (idx < 256 * 20) {
        int o = idx % 20;
        int k = idx / 20;
        g_WoT[k * 20 + o] = Wo[o * 256 + k];
    }
}

__global__ void prep_wc(const float* __restrict__ Wd) {
    int ik = blockIdx.x;
    int i = ik / NUM_INPUT;
    int k = ik % NUM_INPUT;
    int h = threadIdx.x;
    float s = 0.f;
#pragma unroll 8
    for (int j = 0; j < 256; j++) {
        s += g_WfT[j * 256 + h] * __ldg(&Wd[(i * 256 + j) * NUM_INPUT + k]);
    }
    g_WcT[(i * NUM_INPUT + k) * 256 + h] = s;
}

__global__ void prep_cvec(const float* __restrict__ bd, const float* __restrict__ bf) {
    int h = threadIdx.x;
    float s = bf[h];
#pragma unroll 8
    for (int j = 0; j < 256; j++) {
        float bsum = bd[j] + bd[256 + j] + bd[512 + j];
        s += bsum * g_WfT[j * 256 + h];
    }
    g_cvec[h] = s;
}

// ---------------- ff0 GEMM, t-major tiling with delay-segment skipping ------
// Row block = 128 consecutive b's at ONE t. Segments with t<d skipped entirely.
#define GA_BM 128
#define GA_BN 64
#define GA_BK 16

__global__ __launch_bounds__(256) void gemm_ff0(const float* __restrict__ x) {
    __shared__ float As[GA_BK][GA_BM + 4];
    __shared__ float Bs[GA_BK][GA_BN];

    const int tid = threadIdx.x;
    const int tb = blockIdx.y;            // 0..199
    const int t  = tb >> 2;               // 0..49
    const int b0 = (tb & 3) * 128;        // batch base
    const int colBase = blockIdx.x * GA_BN;
    const int tx = tid & 15;
    const int ty = tid >> 4;

    ull accp[4][4];
#pragma unroll
    for (int p = 0; p < 4; p++)
#pragma unroll
        for (int j = 0; j < 4; j++) accp[p][j] = 0ull;

    const int delays[3] = {0, 16, 32};

    const int mm = tid >> 2;
    const int kq = (tid & 3) * 4;
    const int kkB = tid >> 4;
    const int hhB = (tid & 15) * 4;

    for (int i = 0; i < 3; i++) {
        const int d = delays[i];
        if (t < d) continue;              // whole segment contributes zero
        const int ts = t - d;
        const float* __restrict__ Bsrc = &g_WcT[i * NUM_INPUT * 256];
        const float* __restrict__ xrow0 = x + ((size_t)(b0 + mm) * WIN + ts) * NUM_INPUT;
        const float* __restrict__ xrow1 = x + ((size_t)(b0 + mm + 64) * WIN + ts) * NUM_INPUT;

        for (int kb = 0; kb < 704; kb += GA_BK) {
            int kg = kb + kq;
            bool kvalid = (kg < NUM_INPUT);
            float4 v0 = make_float4(0.f, 0.f, 0.f, 0.f);
            float4 v1 = make_float4(0.f, 0.f, 0.f, 0.f);
            if (kvalid) {
                v0 = *reinterpret_cast<const float4*>(xrow0 + kg);
                v1 = *reinterpret_cast<const float4*>(xrow1 + kg);
            }
            As[kq + 0][mm] = v0.x;
            As[kq + 1][mm] = v0.y;
            As[kq + 2][mm] = v0.z;
            As[kq + 3][mm] = v0.w;
            As[kq + 0][mm + 64] = v1.x;
            As[kq + 1][mm + 64] = v1.y;
            As[kq + 2][mm + 64] = v1.z;
            As[kq + 3][mm + 64] = v1.w;

            int kg2 = kb + kkB;
            float4 w = make_float4(0.f, 0.f, 0.f, 0.f);
            if (kg2 < NUM_INPUT)
                w = *reinterpret_cast<const float4*>(Bsrc + kg2 * 256 + colBase + hhB);
            *reinterpret_cast<float4*>(&Bs[kkB][hhB]) = w;

            __syncthreads();

#pragma unroll
            for (int kk = 0; kk < GA_BK; kk++) {
                ulonglong2 a0p = *reinterpret_cast<const ulonglong2*>(&As[kk][ty * 8 + 0]);
                ulonglong2 a1p = *reinterpret_cast<const ulonglong2*>(&As[kk][ty * 8 + 4]);
                float4 bb = *reinterpret_cast<const float4*>(&Bs[kk][tx * 4]);
                ull bp[4] = {pack2(bb.x, bb.x), pack2(bb.y, bb.y),
                             pack2(bb.z, bb.z), pack2(bb.w, bb.w)};
                ull ap[4] = {a0p.x, a0p.y, a1p.x, a1p.y};
#pragma unroll
                for (int p = 0; p < 4; p++)
#pragma unroll
                    for (int j = 0; j < 4; j++) ffma2(accp[p][j], ap[p], bp[j]);
            }
            __syncthreads();
        }
    }

    // epilogue: + cvec; store to (b*WIN+t) layout
#pragma unroll
    for (int p = 0; p < 4; p++) {
#pragma unroll
        for (int j = 0; j < 4; j++) {
            float v0, v1;
            unpack2(accp[p][j], v0, v1);
            int c = colBase + tx * 4 + j;
            int bl0 = b0 + ty * 8 + 2 * p;
            g_ff0[((size_t)bl0 * WIN + t) * 256 + c] = v0 + g_cvec[c];
            g_ff0[((size_t)(bl0 + 1) * WIN + t) * 256 + c] = v1 + g_cvec[c];
        }
    }
}

// ---------------- recurrent scan (R7, proven 660us) ----------------
#define OFFP    0
#define OFFS0   16384
#define OFFS1   (OFFS0 + 5120)
#define OFFWOT  (OFFS1 + 5120)
#define OFFOSM  (OFFWOT + 5120)
#define OFFOTMP (OFFOSM + 160)
#define SCAN_FLOATS (OFFOTMP + 160)    // 32064 floats = 128256 bytes

__device__ __forceinline__ void accum_quad_pf(ull acc[8][2], const float* __restrict__ wg,
                                              int hq4, const float* __restrict__ sp, int kbeg) {
    const float* wp = wg + (size_t)kbeg * 256 + hq4;
    ulonglong2 wbuf[2][4];
#pragma unroll
    for (int c = 0; c < 4; c++) wbuf[0][c] = ldg128(wp + c * 256);
#pragma unroll
    for (int j = 0; j < 8; j++) {
        const int cur = j & 1, nxt = cur ^ 1;
        if (j < 7) {
            const float* q = wp + (size_t)((j + 1) * 4) * 256;
#pragma unroll
            for (int c = 0; c < 4; c++) wbuf[nxt][c] = ldg128(q + c * 256);
        }
#pragma unroll
        for (int c = 0; c < 4; c++) {
            const int k = kbeg + j * 4 + c;
            const ulonglong2* sq = (const ulonglong2*)(sp + k * 20);
            ulonglong2 s01 = sq[0], s23 = sq[1], s45 = sq[2], s67 = sq[3];
            ulonglong2 w = wbuf[cur][c];
            ffma2(acc[0][0], w.x, s01.x); ffma2(acc[0][1], w.y, s01.x);
            ffma2(acc[1][0], w.x, s01.y); ffma2(acc[1][1], w.y, s01.y);
            ffma2(acc[2][0], w.x, s23.x); ffma2(acc[2][1], w.y, s23.x);
            ffma2(acc[3][0], w.x, s23.y); ffma2(acc[3][1], w.y, s23.y);
            ffma2(acc[4][0], w.x, s45.x); ffma2(acc[4][1], w.y, s45.x);
            ffma2(acc[5][0], w.x, s45.y); ffma2(acc[5][1], w.y, s45.y);
            ffma2(acc[6][0], w.x, s67.x); ffma2(acc[6][1], w.y, s67.x);
            ffma2(acc[7][0], w.x, s67.y); ffma2(acc[7][1], w.y, s67.y);
        }
    }
}

__global__ __launch_bounds__(512) void scan_kernel(const float* __restrict__ bf,
                                                   const float* __restrict__ bo,
                                                   float* __restrict__ out) {
    extern __shared__ float sm[];
    ulonglong2* partq = (ulonglong2*)(sm + OFFP);
    float* sp0  = sm + OFFS0;
    float* sp1  = sm + OFFS1;
    float* wot  = sm + OFFWOT;
    float* opart = sm + OFFP;          // alias (barrier-separated)
    float* osm  = sm + OFFOSM;
    float* otmp = sm + OFFOTMP;

    const int tid = threadIdx.x;
    const int ks = tid >> 6;
    const int hq = tid & 63;
    const int hq4 = hq * 4;
    const int b0 = blockIdx.x * 8;

    for (int i = tid; i < 256 * 20; i += 512) wot[i] = g_WoT[i];
    for (int i = tid; i < 5120; i += 512) { sp0[i] = 0.f; sp1[i] = 0.f; }
    __syncthreads();

    ull m0a = 0, m0b = 0, m1a = 0, m1b = 0;
    const ull alpha2 = pack2(ALPHA, ALPHA);
    ull df0a = alpha2, df0b = alpha2, df1a = alpha2, df1b = alpha2;

    float4 bfq = __ldg((const float4*)(bf + 256 + hq4));
    const ull bf1a = pack2(bfq.x, bfq.y);
    const ull bf1b = pack2(bfq.z, bfq.w);

    const int seg = (tid >= 160 && tid < 320) ? 1 : 0;
    const int rr = (tid < 160) ? tid : (tid < 320 ? tid - 160 : 0);
    const int orow = rr / 20, ocol = rr - orow * 20;
    const int okbeg = seg * 128;
    const float bov = (tid < 160) ? __ldg(bo + ocol) : 0.f;
    float o_mem = 0.f, o_dfac = ALPHA, o_sumv = 0.f, o_mot = 0.f;

    const float* __restrict__ wr0g = g_WrT;
    const float* __restrict__ wf1g = g_WfT + 65536;
    const float* __restrict__ wr1g = g_WrT + 65536;

    const int kbeg = ks * 32;

    for (int t = 0; t < WIN; t++) {
        float4 ffv = __ldg((const float4*)(g_ff0 + ((size_t)(b0 + ks) * WIN + t) * 256 + hq4));

        // ---- stage 1: layer0 partials ----
        ull acc[8][2];
#pragma unroll
        for (int r = 0; r < 8; r++) { acc[r][0] = 0ull; acc[r][1] = 0ull; }
        accum_quad_pf(acc, wr0g, hq4, sp0, kbeg);
#pragma unroll
        for (int r = 0; r < 8; r++)
            partq[(r * 8 + ks) * 64 + hq] = make_ulonglong2(acc[r][0], acc[r][1]);
        __syncthreads();                                        // S1

        // ---- stage 2: reduce, membrane0, spikes ----
        {
            ull r0 = 0ull, r1 = 0ull;
#pragma unroll
            for (int j = 0; j < 8; j++) {
                ulonglong2 p = partq[(ks * 8 + j) * 64 + hq];
                r0 = add2(r0, p.x); r1 = add2(r1, p.y);
            }
            r0 = add2(r0, pack2(ffv.x, ffv.y));
            r1 = add2(r1, pack2(ffv.z, ffv.w));
            m0a = fma2n(m0a, df0a, r0);
            m0b = fma2n(m0b, df0b, r1);
            float mx, my, mz, mw;
            unpack2(m0a, mx, my); unpack2(m0b, mz, mw);
            float sx = (mx - THRESH > 0.f) ? 1.f : 0.f;
            float sy = (my - THRESH > 0.f) ? 1.f : 0.f;
            float sz = (mz - THRESH > 0.f) ? 1.f : 0.f;
            float sw = (mw - THRESH > 0.f) ? 1.f : 0.f;
            df0a = pack2(ALPHA * (1.f - sx), ALPHA * (1.f - sy));
            df0b = pack2(ALPHA * (1.f - sz), ALPHA * (1.f - sw));
            *(float2*)(sp0 + (hq4 + 0) * 20 + 2 * ks) = make_float2(sx, sx);
            *(float2*)(sp0 + (hq4 + 1) * 20 + 2 * ks) = make_float2(sy, sy);
            *(float2*)(sp0 + (hq4 + 2) * 20 + 2 * ks) = make_float2(sz, sz);
            *(float2*)(sp0 + (hq4 + 3) * 20 + 2 * ks) = make_float2(sw, sw);
        }
        __syncthreads();                                        // S2

        // ---- stage 3: layer1 partials ----
#pragma unroll
        for (int r = 0; r < 8; r++) { acc[r][0] = 0ull; acc[r][1] = 0ull; }
        accum_quad_pf(acc, wf1g, hq4, sp0, kbeg);
        accum_quad_pf(acc, wr1g, hq4, sp1, kbeg);
#pragma unroll
        for (int r = 0; r < 8; r++)
            partq[(r * 8 + ks) * 64 + hq] = make_ulonglong2(acc[r][0], acc[r][1]);
        __syncthreads();                                        // S3

        // ---- stage 4: reduce, membrane1, spikes ----
        {
            ull r0 = 0ull, r1 = 0ull;
#pragma unroll
            for (int j = 0; j < 8; j++) {
                ulonglong2 p = partq[(ks * 8 + j) * 64 + hq];
                r0 = add2(r0, p.x); r1 = add2(r1, p.y);
            }
            r0 = add2(r0, bf1a);
            r1 = add2(r1, bf1b);
            m1a = fma2n(m1a, df1a, r0);
            m1b = fma2n(m1b, df1b, r1);
            float mx, my, mz, mw;
            unpack2(m1a, mx, my); unpack2(m1b, mz, mw);
            float sx = (mx - THRESH > 0.f) ? 1.f : 0.f;
            float sy = (my - THRESH > 0.f) ? 1.f : 0.f;
            float sz = (mz - THRESH > 0.f) ? 1.f : 0.f;
            float sw = (mw - THRESH > 0.f) ? 1.f : 0.f;
            df1a = pack2(ALPHA * (1.f - sx), ALPHA * (1.f - sy));
            df1b = pack2(ALPHA * (1.f - sz), ALPHA * (1.f - sw));
            *(float2*)(sp1 + (hq4 + 0) * 20 + 2 * ks) = make_float2(sx, sx);
            *(float2*)(sp1 + (hq4 + 1) * 20 + 2 * ks) = make_float2(sy, sy);
            *(float2*)(sp1 + (hq4 + 2) * 20 + 2 * ks) = make_float2(sz, sz);
            *(float2*)(sp1 + (hq4 + 3) * 20 + 2 * ks) = make_float2(sw, sw);
        }
        __syncthreads();                                        // S4

        // ---- stage 5: output partials ----
        if (tid < 320) {
            float oa = 0.f;
#pragma unroll 8
            for (int k = okbeg; k < okbeg + 128; k++) {
                oa += sp1[k * 20 + 2 * orow] * wot[k * 20 + ocol];
            }
            opart[tid] = oa;
        }
        __syncthreads();                                        // S5

        // ---- stage 6: output membrane ----
        if (tid < 160) {
            float oa = opart[tid] + opart[tid + 160] + bov;
            o_mem = o_mem * o_dfac + oa;
            float os = (o_mem - THRESH > 0.f) ? 1.f : 0.f;
            o_dfac = ALPHA * (1.f - os);
            o_sumv += os;
            osm[tid] = o_mem;
        }
        __syncthreads();                                        // S6

        // ---- stage 7: distributed softmax ----
        float e = 0.f;
        if (tid < 160) {
            float mx = -1e30f;
#pragma unroll
            for (int o = 0; o < 20; o++) mx = fmaxf(mx, osm[orow * 20 + o]);
            e = expf(o_mem - mx);
            otmp[tid] = e;
        }
        __syncthreads();                                        // S7

        if (tid < 160) {
            float s = 0.f;
#pragma unroll
            for (int o = 0; o < 20; o++) s += otmp[orow * 20 + o];
            o_mot += e / s;
        }
        // no sync: otmp next written in stage 7 of next step, after S1..S6
    }

    if (tid < 160) {
        int b = b0 + orow;
        out[b * 20 + ocol] = o_sumv / (float)WIN;
        out[BATCH * 20 + b * 20 + ocol] = o_mot;
    }
}

// ---------------- launch ----------------
extern "C" void kernel_launch(void* const* d_in, const int* in_sizes, int n_in,
                              void* d_out, int out_size) {
    const float* x  = (const float*)d_in[0];
    const float* Wd = (const float*)d_in[1];
    const float* bd = (const float*)d_in[2];
    const float* Wf = (const float*)d_in[3];
    const float* bf = (const float*)d_in[4];
    const float* Wr = (const float*)d_in[5];
    const float* Wo = (const float*)d_in[6];
    const float* bo = (const float*)d_in[7];
    float* out = (float*)d_out;

    static bool attr_set = false;
    if (!attr_set) {
        cudaFuncSetAttribute(scan_kernel, cudaFuncAttributeMaxDynamicSharedMemorySize,
                             SCAN_FLOATS * 4);
        attr_set = true;
    }

    prep_transpose<<<512, 256>>>(Wf, Wr, Wo);
    prep_wc<<<3 * NUM_INPUT, 256>>>(Wd);
    prep_cvec<<<1, 256>>>(bd, bf);
    gemm_ff0<<<dim3(NUM_HIDDEN / GA_BN, 4 * WIN), 256>>>(x);
    scan_kernel<<<64, 512, SCAN_FLOATS * 4>>>(bf, bo, out);
}

// round 11
// speedup vs baseline: 2.0750x; 1.1165x over previous
#include <cuda_runtime.h>
#include <cstdint>

#define NUM_INPUT  700
#define NUM_HIDDEN 256
#define NUM_OUTPUT 20
#define WIN        50
#define BATCH      512
#define THRESH     0.3f
#define ALPHA      0.8f

#define M_ROWS (BATCH * WIN)   // 25600

typedef unsigned long long ull;

// ---------------- f32x2 helpers ----------------
__device__ __forceinline__ ull pack2(float x, float y) {
    ull r; asm("mov.b64 %0, {%1, %2};" : "=l"(r) : "f"(x), "f"(y)); return r;
}
__device__ __forceinline__ void unpack2(ull v, float& x, float& y) {
    asm("mov.b64 {%0, %1}, %2;" : "=f"(x), "=f"(y) : "l"(v));
}
__device__ __forceinline__ void ffma2(ull& d, ull a, ull b) {   // d = a*b + d
    asm("fma.rn.f32x2 %0, %1, %2, %0;" : "+l"(d) : "l"(a), "l"(b));
}
__device__ __forceinline__ ull fma2n(ull a, ull b, ull c) {     // a*b + c
    ull d; asm("fma.rn.f32x2 %0, %1, %2, %3;" : "=l"(d) : "l"(a), "l"(b), "l"(c)); return d;
}
__device__ __forceinline__ ull add2(ull a, ull b) {
    ull d; asm("add.rn.f32x2 %0, %1, %2;" : "=l"(d) : "l"(a), "l"(b)); return d;
}
__device__ __forceinline__ ulonglong2 ldg128(const float* p) {
    ulonglong2 v;
    asm("ld.global.nc.v2.u64 {%0, %1}, [%2];" : "=l"(v.x), "=l"(v.y) : "l"(p));
    return v;
}
// coherent (L2) 128-bit load: for data written earlier in the SAME launch
__device__ __forceinline__ float4 ldg_cg128(const float* p) {
    float4 v;
    asm volatile("ld.global.cg.v4.f32 {%0,%1,%2,%3}, [%4];"
                 : "=f"(v.x), "=f"(v.y), "=f"(v.z), "=f"(v.w) : "l"(p));
    return v;
}

// ---------------- device scratch ----------------
__device__ float g_WcT[3 * NUM_INPUT * NUM_HIDDEN];
__device__ float g_WfT[2 * NUM_HIDDEN * NUM_HIDDEN];
__device__ float g_WrT[2 * NUM_HIDDEN * NUM_HIDDEN];
__device__ float g_WoT[NUM_HIDDEN * NUM_OUTPUT];
__device__ float g_cvec[NUM_HIDDEN];
__device__ float g_ff0[M_ROWS * NUM_HIDDEN];
__device__ int   g_flags[4 * WIN];          // per (t, chunk) tile counter (2 colhalves)

// ---------------- prep kernels ----------------
__global__ void zero_flags() {
    if (threadIdx.x < 4 * WIN) g_flags[threadIdx.x] = 0;
}

__global__ void prep_transpose(const float* __restrict__ Wf,
                               const float* __restrict__ Wr,
                               const float* __restrict__ Wo) {
    int idx = blockIdx.x * 256 + threadIdx.x;
    if (idx < 2 * 256 * 256) {
        int h = idx & 255;
        int k = (idx >> 8) & 255;
        int l = idx >> 16;
        g_WfT[(l * 256 + k) * 256 + h] = Wf[(l * 256 + h) * 256 + k];
        g_WrT[(l * 256 + k) * 256 + h] = Wr[(l * 256 + h) * 256 + k];
    }
    if (idx < 256 * 20) {
        int o = idx % 20;
        int k = idx / 20;
        g_WoT[k * 20 + o] = Wo[o * 256 + k];
    }
}

__global__ void prep_wc(const float* __restrict__ Wd) {
    int ik = blockIdx.x;
    int i = ik / NUM_INPUT;
    int k = ik % NUM_INPUT;
    int h = threadIdx.x;
    float s = 0.f;
#pragma unroll 8
    for (int j = 0; j < 256; j++) {
        s += g_WfT[j * 256 + h] * __ldg(&Wd[(i * 256 + j) * NUM_INPUT + k]);
    }
    g_WcT[(i * NUM_INPUT + k) * 256 + h] = s;
}

__global__ void prep_cvec(const float* __restrict__ bd, const float* __restrict__ bf) {
    int h = threadIdx.x;
    float s = bf[h];
#pragma unroll 8
    for (int j = 0; j < 256; j++) {
        float bsum = bd[j] + bd[256 + j] + bd[512 + j];
        s += bsum * g_WfT[j * 256 + h];
    }
    g_cvec[h] = s;
}

// ---------------- fused kernel ----------------
// blocks 0..63: scan (one per 8 batch rows). blocks 64..463: gemm tiles.
// gemm tile gid-64: tile = (gid-64)>>1 in t-ascending order, colhalf = (gid-64)&1.
#define FK_SCAN_BLOCKS 64
#define FK_GEMM_BLOCKS 400

// scan smem layout (floats)
#define OFFP    0
#define OFFS0   16384
#define OFFS1   (OFFS0 + 5120)
#define OFFWOT  (OFFS1 + 5120)
#define OFFOSM  (OFFWOT + 5120)
#define OFFOTMP (OFFOSM + 160)
#define SCAN_FLOATS (OFFOTMP + 160)    // 32064 floats = 128256 bytes

__device__ __forceinline__ void accum_quad_pf(ull acc[8][2], const float* __restrict__ wg,
                                              int hq4, const float* __restrict__ sp, int kbeg) {
    const float* wp = wg + (size_t)kbeg * 256 + hq4;
    ulonglong2 wbuf[2][4];
#pragma unroll
    for (int cc = 0; cc < 4; cc++) wbuf[0][cc] = ldg128(wp + cc * 256);
#pragma unroll
    for (int j = 0; j < 8; j++) {
        const int cur = j & 1, nxt = cur ^ 1;
        if (j < 7) {
            const float* q = wp + (size_t)((j + 1) * 4) * 256;
#pragma unroll
            for (int cc = 0; cc < 4; cc++) wbuf[nxt][cc] = ldg128(q + cc * 256);
        }
#pragma unroll
        for (int cc = 0; cc < 4; cc++) {
            const int k = kbeg + j * 4 + cc;
            const ulonglong2* sq = (const ulonglong2*)(sp + k * 20);
            ulonglong2 s01 = sq[0], s23 = sq[1], s45 = sq[2], s67 = sq[3];
            ulonglong2 w = wbuf[cur][cc];
            ffma2(acc[0][0], w.x, s01.x); ffma2(acc[0][1], w.y, s01.x);
            ffma2(acc[1][0], w.x, s01.y); ffma2(acc[1][1], w.y, s01.y);
            ffma2(acc[2][0], w.x, s23.x); ffma2(acc[2][1], w.y, s23.x);
            ffma2(acc[3][0], w.x, s23.y); ffma2(acc[3][1], w.y, s23.y);
            ffma2(acc[4][0], w.x, s45.x); ffma2(acc[4][1], w.y, s45.x);
            ffma2(acc[5][0], w.x, s45.y); ffma2(acc[5][1], w.y, s45.y);
            ffma2(acc[6][0], w.x, s67.x); ffma2(acc[6][1], w.y, s67.x);
            ffma2(acc[7][0], w.x, s67.y); ffma2(acc[7][1], w.y, s67.y);
        }
    }
}

__global__ __launch_bounds__(512, 1) void fused_kernel(const float* __restrict__ x,
                                                       const float* __restrict__ bf,
                                                       const float* __restrict__ bo,
                                                       float* __restrict__ out) {
    extern __shared__ float sm[];
    const int tid = threadIdx.x;

    if (blockIdx.x >= FK_SCAN_BLOCKS) {
        // ==================== GEMM tile ====================
        const int gid = blockIdx.x - FK_SCAN_BLOCKS;
        const int tile = gid >> 1;              // 0..199, t-ascending
        const int h0 = (gid & 1) << 7;          // 0 or 128
        const int t = tile >> 2;
        const int b0g = (tile & 3) << 7;

        float (*As)[132] = reinterpret_cast<float(*)[132]>(sm);
        float (*Bs)[128] = reinterpret_cast<float(*)[128]>(sm + 16 * 132);

        const int lane = tid & 31;
        const int warp = tid >> 5;
        const int arow = tid >> 2;              // 0..127
        const int akq  = (tid & 3) * 4;         // 0,4,8,12
        const int bk   = tid >> 5;              // 0..15
        const int bcol = lane * 4;

        ull accp[4][4];
#pragma unroll
        for (int p = 0; p < 4; p++)
#pragma unroll
            for (int j = 0; j < 4; j++) accp[p][j] = 0ull;

        for (int seg = 0; seg < 3; seg++) {
            const int d = seg * 16;
            if (t < d) continue;
            const int ts = t - d;
            const float* __restrict__ xrow = x + ((size_t)(b0g + arow) * WIN + ts) * NUM_INPUT;
            const float* __restrict__ Bsrc = g_WcT + (size_t)seg * NUM_INPUT * 256;

            for (int kb = 0; kb < 704; kb += 16) {
                int kg = kb + akq;
                float4 v = make_float4(0.f, 0.f, 0.f, 0.f);
                if (kg < NUM_INPUT) v = __ldg((const float4*)(xrow + kg));
                As[akq + 0][arow] = v.x;
                As[akq + 1][arow] = v.y;
                As[akq + 2][arow] = v.z;
                As[akq + 3][arow] = v.w;

                int kg2 = kb + bk;
                float4 w = make_float4(0.f, 0.f, 0.f, 0.f);
                if (kg2 < NUM_INPUT)
                    w = __ldg((const float4*)(Bsrc + (size_t)kg2 * 256 + h0 + bcol));
                *(float4*)&Bs[bk][bcol] = w;

                __syncthreads();
#pragma unroll
                for (int kk = 0; kk < 16; kk++) {
                    ulonglong2 a01 = *(const ulonglong2*)&As[kk][warp * 8 + 0];
                    ulonglong2 a23 = *(const ulonglong2*)&As[kk][warp * 8 + 4];
                    float4 bb = *(const float4*)&Bs[kk][lane * 4];
                    ull bp[4] = {pack2(bb.x, bb.x), pack2(bb.y, bb.y),
                                 pack2(bb.z, bb.z), pack2(bb.w, bb.w)};
                    ull ap[4] = {a01.x, a01.y, a23.x, a23.y};
#pragma unroll
                    for (int p = 0; p < 4; p++)
#pragma unroll
                        for (int j = 0; j < 4; j++) ffma2(accp[p][j], ap[p], bp[j]);
                }
                __syncthreads();
            }
        }

        // epilogue: + cvec, store t-major rows; then publish flag
        {
            float4 cv = __ldg((const float4*)(g_cvec + h0 + lane * 4));
#pragma unroll
            for (int p = 0; p < 4; p++) {
                float lo[4], hi[4];
#pragma unroll
                for (int j = 0; j < 4; j++) unpack2(accp[p][j], lo[j], hi[j]);
                float4 o0 = make_float4(lo[0] + cv.x, lo[1] + cv.y, lo[2] + cv.z, lo[3] + cv.w);
                float4 o1 = make_float4(hi[0] + cv.x, hi[1] + cv.y, hi[2] + cv.z, hi[3] + cv.w);
                int r0 = b0g + warp * 8 + 2 * p;
                *(float4*)(g_ff0 + ((size_t)r0 * WIN + t) * 256 + h0 + lane * 4) = o0;
                *(float4*)(g_ff0 + ((size_t)(r0 + 1) * WIN + t) * 256 + h0 + lane * 4) = o1;
            }
        }
        __threadfence();
        __syncthreads();
        if (tid == 0) atomicAdd(&g_flags[tile], 1);
        return;
    }

    // ==================== SCAN block ====================
    ulonglong2* partq = (ulonglong2*)(sm + OFFP);
    float* sp0  = sm + OFFS0;
    float* sp1  = sm + OFFS1;
    float* wot  = sm + OFFWOT;
    float* opart = sm + OFFP;          // alias (barrier-separated)
    float* osm  = sm + OFFOSM;
    float* otmp = sm + OFFOTMP;

    const int ks = tid >> 6;
    const int hq = tid & 63;
    const int hq4 = hq * 4;
    const int b0 = blockIdx.x * 8;
    const int chunk = blockIdx.x >> 4;         // 128-batch chunk

    for (int i = tid; i < 256 * 20; i += 512) wot[i] = g_WoT[i];
    for (int i = tid; i < 5120; i += 512) { sp0[i] = 0.f; sp1[i] = 0.f; }
    __syncthreads();

    ull m0a = 0, m0b = 0, m1a = 0, m1b = 0;
    const ull alpha2 = pack2(ALPHA, ALPHA);
    ull df0a = alpha2, df0b = alpha2, df1a = alpha2, df1b = alpha2;

    float4 bfq = __ldg((const float4*)(bf + 256 + hq4));
    const ull bf1a = pack2(bfq.x, bfq.y);
    const ull bf1b = pack2(bfq.z, bfq.w);

    const int seg = (tid >= 160 && tid < 320) ? 1 : 0;
    const int rr = (tid < 160) ? tid : (tid < 320 ? tid - 160 : 0);
    const int orow = rr / 20, ocol = rr - orow * 20;
    const int okbeg = seg * 128;
    const float bov = (tid < 160) ? __ldg(bo + ocol) : 0.f;
    float o_mem = 0.f, o_dfac = ALPHA, o_sumv = 0.f, o_mot = 0.f;

    const float* __restrict__ wr0g = g_WrT;
    const float* __restrict__ wf1g = g_WfT + 65536;
    const float* __restrict__ wr1g = g_WrT + 65536;

    const int kbeg = ks * 32;

    for (int t = 0; t < WIN; t++) {
        // ---- stage 1: layer0 partials (no ff0 dependency) ----
        ull acc[8][2];
#pragma unroll
        for (int r = 0; r < 8; r++) { acc[r][0] = 0ull; acc[r][1] = 0ull; }
        accum_quad_pf(acc, wr0g, hq4, sp0, kbeg);
#pragma unroll
        for (int r = 0; r < 8; r++)
            partq[(r * 8 + ks) * 64 + hq] = make_ulonglong2(acc[r][0], acc[r][1]);

        // wait for gemm tile (t, chunk): both column halves done
        if (tid == 0) {
            volatile int* fl = g_flags + (t * 4 + chunk);
            while (*fl != 2) __nanosleep(128);
        }
        __threadfence();
        __syncthreads();                                        // S1 (+ data ready)

        // ---- stage 2: reduce, membrane0, spikes ----
        {
            float4 ffv = ldg_cg128(g_ff0 + ((size_t)(b0 + ks) * WIN + t) * 256 + hq4);
            ull r0 = 0ull, r1 = 0ull;
#pragma unroll
            for (int j = 0; j < 8; j++) {
                ulonglong2 p = partq[(ks * 8 + j) * 64 + hq];
                r0 = add2(r0, p.x); r1 = add2(r1, p.y);
            }
            r0 = add2(r0, pack2(ffv.x, ffv.y));
            r1 = add2(r1, pack2(ffv.z, ffv.w));
            m0a = fma2n(m0a, df0a, r0);
            m0b = fma2n(m0b, df0b, r1);
            float mx, my, mz, mw;
            unpack2(m0a, mx, my); unpack2(m0b, mz, mw);
            float sx = (mx - THRESH > 0.f) ? 1.f : 0.f;
            float sy = (my - THRESH > 0.f) ? 1.f : 0.f;
            float sz = (mz - THRESH > 0.f) ? 1.f : 0.f;
            float sw = (mw - THRESH > 0.f) ? 1.f : 0.f;
            df0a = pack2(ALPHA * (1.f - sx), ALPHA * (1.f - sy));
            df0b = pack2(ALPHA * (1.f - sz), ALPHA * (1.f - sw));
            *(float2*)(sp0 + (hq4 + 0) * 20 + 2 * ks) = make_float2(sx, sx);
            *(float2*)(sp0 + (hq4 + 1) * 20 + 2 * ks) = make_float2(sy, sy);
            *(float2*)(sp0 + (hq4 + 2) * 20 + 2 * ks) = make_float2(sz, sz);
            *(float2*)(sp0 + (hq4 + 3) * 20 + 2 * ks) = make_float2(sw, sw);
        }
        __syncthreads();                                        // S2

        // ---- stage 3: layer1 partials ----
#pragma unroll
        for (int r = 0; r < 8; r++) { acc[r][0] = 0ull; acc[r][1] = 0ull; }
        accum_quad_pf(acc, wf1g, hq4, sp0, kbeg);
        accum_quad_pf(acc, wr1g, hq4, sp1, kbeg);
#pragma unroll
        for (int r = 0; r < 8; r++)
            partq[(r * 8 + ks) * 64 + hq] = make_ulonglong2(acc[r][0], acc[r][1]);
        __syncthreads();                                        // S3

        // ---- stage 4: reduce, membrane1, spikes ----
        {
            ull r0 = 0ull, r1 = 0ull;
#pragma unroll
            for (int j = 0; j < 8; j++) {
                ulonglong2 p = partq[(ks * 8 + j) * 64 + hq];
                r0 = add2(r0, p.x); r1 = add2(r1, p.y);
            }
            r0 = add2(r0, bf1a);
            r1 = add2(r1, bf1b);
            m1a = fma2n(m1a, df1a, r0);
            m1b = fma2n(m1b, df1b, r1);
            float mx, my, mz, mw;
            unpack2(m1a, mx, my); unpack2(m1b, mz, mw);
            float sx = (mx - THRESH > 0.f) ? 1.f : 0.f;
            float sy = (my - THRESH > 0.f) ? 1.f : 0.f;
            float sz = (mz - THRESH > 0.f) ? 1.f : 0.f;
            float sw = (mw - THRESH > 0.f) ? 1.f : 0.f;
            df1a = pack2(ALPHA * (1.f - sx), ALPHA * (1.f - sy));
            df1b = pack2(ALPHA * (1.f - sz), ALPHA * (1.f - sw));
            *(float2*)(sp1 + (hq4 + 0) * 20 + 2 * ks) = make_float2(sx, sx);
            *(float2*)(sp1 + (hq4 + 1) * 20 + 2 * ks) = make_float2(sy, sy);
            *(float2*)(sp1 + (hq4 + 2) * 20 + 2 * ks) = make_float2(sz, sz);
            *(float2*)(sp1 + (hq4 + 3) * 20 + 2 * ks) = make_float2(sw, sw);
        }
        __syncthreads();                                        // S4

        // ---- stage 5: output partials ----
        if (tid < 320) {
            float oa = 0.f;
#pragma unroll 8
            for (int k = okbeg; k < okbeg + 128; k++) {
                oa += sp1[k * 20 + 2 * orow] * wot[k * 20 + ocol];
            }
            opart[tid] = oa;
        }
        __syncthreads();                                        // S5

        // ---- stage 6: output membrane ----
        if (tid < 160) {
            float oa = opart[tid] + opart[tid + 160] + bov;
            o_mem = o_mem * o_dfac + oa;
            float os = (o_mem - THRESH > 0.f) ? 1.f : 0.f;
            o_dfac = ALPHA * (1.f - os);
            o_sumv += os;
            osm[tid] = o_mem;
        }
        __syncthreads();                                        // S6

        // ---- stage 7: distributed softmax ----
        float e = 0.f;
        if (tid < 160) {
            float mx = -1e30f;
#pragma unroll
            for (int o = 0; o < 20; o++) mx = fmaxf(mx, osm[orow * 20 + o]);
            e = expf(o_mem - mx);
            otmp[tid] = e;
        }
        __syncthreads();                                        // S7

        if (tid < 160) {
            float s = 0.f;
#pragma unroll
            for (int o = 0; o < 20; o++) s += otmp[orow * 20 + o];
            o_mot += e / s;
        }
        // no sync needed: otmp rewritten only after S6 of next step
    }

    if (tid < 160) {
        int b = b0 + orow;
        out[b * 20 + ocol] = o_sumv / (float)WIN;
        out[BATCH * 20 + b * 20 + ocol] = o_mot;
    }
}

// ---------------- launch ----------------
extern "C" void kernel_launch(void* const* d_in, const int* in_sizes, int n_in,
                              void* d_out, int out_size) {
    const float* x  = (const float*)d_in[0];
    const float* Wd = (const float*)d_in[1];
    const float* bd = (const float*)d_in[2];
    const float* Wf = (const float*)d_in[3];
    const float* bf = (const float*)d_in[4];
    const float* Wr = (const float*)d_in[5];
    const float* Wo = (const float*)d_in[6];
    const float* bo = (const float*)d_in[7];
    float* out = (float*)d_out;

    static bool attr_set = false;
    if (!attr_set) {
        cudaFuncSetAttribute(fused_kernel, cudaFuncAttributeMaxDynamicSharedMemorySize,
                             SCAN_FLOATS * 4);
        attr_set = true;
    }

    zero_flags<<<1, 256>>>();
    prep_transpose<<<512, 256>>>(Wf, Wr, Wo);
    prep_wc<<<3 * NUM_INPUT, 256>>>(Wd);
    prep_cvec<<<1, 256>>>(bd, bf);
    fused_kernel<<<FK_SCAN_BLOCKS + FK_GEMM_BLOCKS, 512, SCAN_FLOATS * 4>>>(x, bf, bo, out);
}